// round 4
// baseline (speedup 1.0000x reference)
#include <cuda_runtime.h>
#include <cuda_bf16.h>
#include <cstdint>
#include <math.h>

#define NPTS 8192
#define DIM  256
#define NCLS 10
#define KNN  3
#define NT   64          // 8192/128 tiles per dim
#define NTRI (NT*(NT+1)/2)

// ---------------- device scratch ----------------
__device__ float g_d2[(size_t)NPTS * NPTS];          // clamped squared distances (256 MB)
__device__ float g_sq[NPTS];
__device__ int   g_m[NPTS];
__device__ float g_anchor[NPTS];
__device__ float4 g_top4[(size_t)NPTS * NT];         // per-(row, col-tile) sorted-4 partials (8 MB)
__device__ double g_part[64];
__device__ __nv_bfloat16 g_Xhi[(size_t)NPTS * DIM];  // 4 MB
__device__ __nv_bfloat16 g_Xlo[(size_t)NPTS * DIM];  // 4 MB

// ---------------- helpers ----------------
__device__ __forceinline__ uint32_t smem_u32(const void* p) {
    uint32_t a;
    asm("{ .reg .u64 t; cvta.to.shared.u64 t, %1; cvt.u32.u64 %0, t; }" : "=r"(a) : "l"(p));
    return a;
}
__device__ __forceinline__ void cp16(uint32_t dst, const void* src) {
    asm volatile("cp.async.cg.shared.global [%0], [%1], 16;" :: "r"(dst), "l"(src));
}
#define CP_COMMIT() asm volatile("cp.async.commit_group;" ::: "memory")
#define CP_WAIT0()  asm volatile("cp.async.wait_group 0;" ::: "memory")

#define MMA16816(d, a, b) \
  asm volatile("mma.sync.aligned.m16n8k16.row.col.f32.bf16.bf16.f32 " \
      "{%0,%1,%2,%3}, {%4,%5,%6,%7}, {%8,%9}, {%0,%1,%2,%3};" \
      : "+f"(d[0]), "+f"(d[1]), "+f"(d[2]), "+f"(d[3]) \
      : "r"(a[0]), "r"(a[1]), "r"(a[2]), "r"(a[3]), "r"(b[0]), "r"(b[1]))

__device__ __forceinline__ void ins4(float v, float& b0, float& b1, float& b2, float& b3) {
    if (v < b3) {
        if (v < b2) {
            b3 = b2;
            if (v < b1) {
                b2 = b1;
                if (v < b0) { b1 = b0; b0 = v; } else b1 = v;
            } else b2 = v;
        } else b3 = v;
    }
}
__device__ __forceinline__ void merge_sorted4(float* a, const float* b) {
    float r0, r1, r2, r3;
    int i = 0, j = 0;
    r0 = (a[0] <= b[0]) ? a[i++] : b[j++];
    r1 = (a[i] <= b[j]) ? a[i++] : b[j++];
    r2 = (a[i] <= b[j]) ? a[i++] : b[j++];
    r3 = (a[i] <= b[j]) ? a[i++] : b[j++];
    a[0] = r0; a[1] = r1; a[2] = r2; a[3] = r3;
}

// ---------------- kernel 1: split X -> bf16 hi/lo + squared norms ----------------
__global__ void __launch_bounds__(256) prep_kernel(const float* __restrict__ X) {
    int row  = blockIdx.x * 8 + (threadIdx.x >> 5);
    int lane = threadIdx.x & 31;
    const float* xr = X + (size_t)row * DIM + lane * 8;
    float4 v0 = *(const float4*)xr;
    float4 v1 = *(const float4*)(xr + 4);
    float v[8] = {v0.x, v0.y, v0.z, v0.w, v1.x, v1.y, v1.z, v1.w};
    uint32_t ph[4], pl[4];
    float s = 0.f;
    #pragma unroll
    for (int q = 0; q < 4; q++) {
        float a = v[2 * q], b = v[2 * q + 1];
        __nv_bfloat16 ha = __float2bfloat16(a), hb = __float2bfloat16(b);
        __nv_bfloat16 la = __float2bfloat16(a - __bfloat162float(ha));
        __nv_bfloat16 lb = __float2bfloat16(b - __bfloat162float(hb));
        ph[q] = ((uint32_t)__bfloat16_as_ushort(hb) << 16) | __bfloat16_as_ushort(ha);
        pl[q] = ((uint32_t)__bfloat16_as_ushort(lb) << 16) | __bfloat16_as_ushort(la);
        s = fmaf(a, a, fmaf(b, b, s));
    }
    size_t off = (size_t)row * DIM + lane * 8;
    *(uint4*)(g_Xhi + off) = make_uint4(ph[0], ph[1], ph[2], ph[3]);
    *(uint4*)(g_Xlo + off) = make_uint4(pl[0], pl[1], pl[2], pl[3]);
    #pragma unroll
    for (int o = 16; o; o >>= 1) s += __shfl_xor_sync(0xffffffffu, s, o);
    if (lane == 0) g_sq[row] = s;
}

// ---------------- kernel 2: symmetric split-bf16 GEMM + fused top-4 partials --------
#define TPITCH   80
#define TILE_SB  (128 * TPITCH)
#define STAGE_SB (4 * TILE_SB)
#define BUFPITCH 132
#define S4OFF    (128 * BUFPITCH * 4)    // 67584, after the d2 staging buffer
#define GSMEM    (2 * STAGE_SB)          // 81920 (also covers S4OFF + 4KB)

__global__ void __launch_bounds__(256) gemm_kernel(const int* __restrict__ y) {
    extern __shared__ char smem[];
    __shared__ int ys_rc[256];           // [0:128) row classes, [128:256) col classes
    const int tid = threadIdx.x, wid = tid >> 5, lane = tid & 31;
    const int warp_m = wid >> 2, warp_n = wid & 3;

    // decode triangular tile index
    int idx = blockIdx.x;
    int bi = (int)((2 * NT + 1 - sqrtf((float)((2 * NT + 1) * (2 * NT + 1) - 8 * idx))) * 0.5f);
    while ((bi + 1) * NT - ((bi + 1) * bi) / 2 <= idx) bi++;
    while (bi * NT - (bi * (bi - 1)) / 2 > idx) bi--;
    int bj = bi + (idx - (bi * NT - (bi * (bi - 1)) / 2));
    const int row0 = bi * 128, col0 = bj * 128;

    if (tid < 128) ys_rc[tid] = y[row0 + tid];
    else           ys_rc[tid] = y[col0 + tid - 128];

    const __nv_bfloat16* srcs[4] = {
        g_Xhi + (size_t)row0 * DIM, g_Xlo + (size_t)row0 * DIM,
        g_Xhi + (size_t)col0 * DIM, g_Xlo + (size_t)col0 * DIM };

    const uint32_t sb = smem_u32(smem);

    auto load_stage = [&](int stage, int kc) {
        uint32_t base = sb + stage * STAGE_SB;
        #pragma unroll
        for (int i = 0; i < 8; i++) {
            int gid = tid + i * 256;
            int tile = gid >> 9, rem = gid & 511;
            int r = rem >> 2, c = rem & 3;
            cp16(base + tile * TILE_SB + r * TPITCH + c * 16,
                 srcs[tile] + (size_t)r * DIM + kc * 32 + c * 8);
        }
        CP_COMMIT();
    };

    float acc[4][4][4];
    #pragma unroll
    for (int mt = 0; mt < 4; mt++)
        #pragma unroll
        for (int nt = 0; nt < 4; nt++)
            #pragma unroll
            for (int e = 0; e < 4; e++) acc[mt][nt][e] = 0.f;

    load_stage(0, 0);
    CP_WAIT0(); __syncthreads();

    const int frag_r = lane >> 2;
    const int frag_k = lane & 3;

    #pragma unroll 1
    for (int kc = 0; kc < 8; kc++) {
        if (kc < 7) load_stage((kc + 1) & 1, kc + 1);

        const char* st = smem + (kc & 1) * STAGE_SB;
        #pragma unroll
        for (int ks = 0; ks < 2; ks++) {
            uint32_t ah[4][4], al[4][4], bh[4][2], bl[4][2];
            #pragma unroll
            for (int mt = 0; mt < 4; mt++) {
                int r = warp_m * 64 + mt * 16 + frag_r;
                const char* pa = st + r * TPITCH + ks * 32 + frag_k * 4;
                ah[mt][0] = *(const uint32_t*)(pa);
                ah[mt][1] = *(const uint32_t*)(pa + 8 * TPITCH);
                ah[mt][2] = *(const uint32_t*)(pa + 16);
                ah[mt][3] = *(const uint32_t*)(pa + 8 * TPITCH + 16);
                const char* pl = pa + TILE_SB;
                al[mt][0] = *(const uint32_t*)(pl);
                al[mt][1] = *(const uint32_t*)(pl + 8 * TPITCH);
                al[mt][2] = *(const uint32_t*)(pl + 16);
                al[mt][3] = *(const uint32_t*)(pl + 8 * TPITCH + 16);
            }
            #pragma unroll
            for (int nt = 0; nt < 4; nt++) {
                int n = warp_n * 32 + nt * 8 + frag_r;
                const char* pb = st + 2 * TILE_SB + n * TPITCH + ks * 32 + frag_k * 4;
                bh[nt][0] = *(const uint32_t*)(pb);
                bh[nt][1] = *(const uint32_t*)(pb + 16);
                bl[nt][0] = *(const uint32_t*)(pb + TILE_SB);
                bl[nt][1] = *(const uint32_t*)(pb + TILE_SB + 16);
            }
            #pragma unroll
            for (int mt = 0; mt < 4; mt++)
                #pragma unroll
                for (int nt = 0; nt < 4; nt++) {
                    MMA16816(acc[mt][nt], ah[mt], bh[nt]);
                    MMA16816(acc[mt][nt], ah[mt], bl[nt]);
                    MMA16816(acc[mt][nt], al[mt], bh[nt]);
                }
        }
        if (kc < 7) { CP_WAIT0(); __syncthreads(); }
    }
    __syncthreads();

    float sqi[8], sqj[8];
    #pragma unroll
    for (int mt = 0; mt < 4; mt++) {
        sqi[2 * mt]     = g_sq[row0 + warp_m * 64 + mt * 16 + frag_r];
        sqi[2 * mt + 1] = g_sq[row0 + warp_m * 64 + mt * 16 + frag_r + 8];
    }
    #pragma unroll
    for (int nt = 0; nt < 4; nt++) {
        sqj[2 * nt]     = g_sq[col0 + warp_n * 32 + nt * 8 + 2 * frag_k];
        sqj[2 * nt + 1] = g_sq[col0 + warp_n * 32 + nt * 8 + 2 * frag_k + 1];
    }

    // stage d2 tile in smem
    float* buf = (float*)smem;
    #pragma unroll
    for (int mt = 0; mt < 4; mt++) {
        int r0 = warp_m * 64 + mt * 16 + frag_r;
        #pragma unroll
        for (int nt = 0; nt < 4; nt++) {
            int c0 = warp_n * 32 + nt * 8 + 2 * frag_k;
            buf[r0 * BUFPITCH + c0]           = fmaxf(fmaf(-2.f, acc[mt][nt][0], sqi[2*mt]   + sqj[2*nt]),   0.f);
            buf[r0 * BUFPITCH + c0 + 1]       = fmaxf(fmaf(-2.f, acc[mt][nt][1], sqi[2*mt]   + sqj[2*nt+1]), 0.f);
            buf[(r0 + 8) * BUFPITCH + c0]     = fmaxf(fmaf(-2.f, acc[mt][nt][2], sqi[2*mt+1] + sqj[2*nt]),   0.f);
            buf[(r0 + 8) * BUFPITCH + c0 + 1] = fmaxf(fmaf(-2.f, acc[mt][nt][3], sqi[2*mt+1] + sqj[2*nt+1]), 0.f);
        }
    }
    __syncthreads();

    float4* s4 = (float4*)(smem + S4OFF);

    // straight d2 write
    {
        int r = tid >> 1, cq = (tid & 1) * 16;
        float* orow = g_d2 + (size_t)(row0 + r) * NPTS + col0;
        const float* brow = buf + r * BUFPITCH;
        #pragma unroll
        for (int q = 0; q < 16; q++)
            *(float4*)(orow + (cq + q) * 4) = *(const float4*)(brow + (cq + q) * 4);
    }

    // straight top-4 partial: 2 threads per row scan 64 cols each (same-class masked)
    {
        int r = tid >> 1, h = tid & 1;
        int yr = ys_rc[r];
        const float* br = buf + r * BUFPITCH + h * 64;
        const int* yc = ys_rc + 128 + h * 64;
        float b0 = INFINITY, b1 = INFINITY, b2 = INFINITY, b3 = INFINITY;
        #pragma unroll 8
        for (int s = 0; s < 64; s++)
            if (yc[s] == yr) ins4(br[s], b0, b1, b2, b3);
        s4[tid] = make_float4(b0, b1, b2, b3);
    }
    __syncthreads();
    if ((tid & 1) == 0) {
        float a[4] = {s4[tid].x, s4[tid].y, s4[tid].z, s4[tid].w};
        float b[4] = {s4[tid + 1].x, s4[tid + 1].y, s4[tid + 1].z, s4[tid + 1].w};
        merge_sorted4(a, b);
        g_top4[(size_t)(row0 + (tid >> 1)) * NT + bj] = make_float4(a[0], a[1], a[2], a[3]);
    }

    if (bi != bj) {
        // transposed d2 write
        {
            int rr = tid & 127, cb = tid >> 7;
            #pragma unroll
            for (int it = 0; it < 64; it++) {
                int c = cb + it * 2;
                g_d2[(size_t)(col0 + c) * NPTS + row0 + rr] = buf[rr * BUFPITCH + c];
            }
        }
        // transposed top-4 partial: 2 threads per column scan 64 rows each
        __syncthreads();
        {
            int c = tid >> 1, h = tid & 1;
            int yc = ys_rc[128 + c];
            const int* yrw = ys_rc + h * 64;
            float b0 = INFINITY, b1 = INFINITY, b2 = INFINITY, b3 = INFINITY;
            #pragma unroll 8
            for (int s = 0; s < 64; s++)
                if (yrw[s] == yc) ins4(buf[(h * 64 + s) * BUFPITCH + c], b0, b1, b2, b3);
            s4[tid] = make_float4(b0, b1, b2, b3);
        }
        __syncthreads();
        if ((tid & 1) == 0) {
            float a[4] = {s4[tid].x, s4[tid].y, s4[tid].z, s4[tid].w};
            float b[4] = {s4[tid + 1].x, s4[tid + 1].y, s4[tid + 1].z, s4[tid + 1].w};
            merge_sorted4(a, b);
            g_top4[(size_t)(col0 + (tid >> 1)) * NT + bi] = make_float4(a[0], a[1], a[2], a[3]);
        }
    }
}

// ---------------- kernel 3a: anchor reduce (warp per row) ----------------
__global__ void __launch_bounds__(256) anchor_kernel() {
    const int tid = threadIdx.x, wid = tid >> 5, lane = tid & 31;
    const int row = blockIdx.x * 8 + wid;
    const float4* p = g_top4 + (size_t)row * NT;
    float4 va = p[2 * lane], vb = p[2 * lane + 1];
    float q[4] = {va.x, va.y, va.z, va.w};
    float b[4] = {vb.x, vb.y, vb.z, vb.w};
    merge_sorted4(q, b);
    #pragma unroll
    for (int off = 16; off; off >>= 1) {
        float o[4];
        #pragma unroll
        for (int e = 0; e < 4; e++) o[e] = __shfl_xor_sync(0xffffffffu, q[e], off);
        merge_sorted4(q, o);
    }
    if (lane == 0) g_anchor[row] = q[3];
}

// ---------------- kernel 3b: count (warp per row, streaming) ----------------
__global__ void __launch_bounds__(256) count_kernel() {
    const int tid = threadIdx.x, wid = tid >> 5, lane = tid & 31;
    const int row = blockIdx.x * 8 + wid;
    const float anc = g_anchor[row];
    const float4* p = (const float4*)(g_d2 + (size_t)row * NPTS);
    int cnt = 0;
    #pragma unroll 4
    for (int i = lane; i < NPTS / 4; i += 32) {
        float4 v = __ldcs(p + i);
        cnt += (v.x < anc) + (v.y < anc) + (v.z < anc) + (v.w < anc);
    }
    #pragma unroll
    for (int o = 16; o; o >>= 1) cnt += __shfl_xor_sync(0xffffffffu, cnt, o);
    if (lane == 0) g_m[row] = cnt - 1;
}

// ---------------- kernel 4: finalize ----------------
__device__ double digamma_d(double x) {
    double r = 0.0;
    while (x < 6.0) { r -= 1.0 / x; x += 1.0; }
    double f = 1.0 / (x * x);
    double ser = f * (1.0 / 12.0 - f * (1.0 / 120.0 - f * (1.0 / 252.0
               - f * (1.0 / 240.0 - f * (1.0 / 132.0)))));
    return r + log(x) - 0.5 / x - ser;
}

__global__ void fin_part_kernel() {
    __shared__ double sd[128];
    const int tid = threadIdx.x;
    int r = blockIdx.x * 128 + tid;
    float arg = (float)g_m[r] + 1e-7f;
    sd[tid] = digamma_d((double)arg);
    __syncthreads();
    for (int off = 64; off; off >>= 1) {
        if (tid < off) sd[tid] += sd[tid + off];
        __syncthreads();
    }
    if (tid == 0) g_part[blockIdx.x] = sd[0];
}

__global__ void fin2_kernel(const int* __restrict__ y, float* __restrict__ out) {
    __shared__ int hist[NCLS];
    const int tid = threadIdx.x;
    if (tid < NCLS) hist[tid] = 0;
    __syncthreads();
    for (int j = tid; j < NPTS; j += 256) atomicAdd(&hist[y[j]], 1);
    __syncthreads();
    if (tid == 0) {
        double s = 0.0;
        for (int b = 0; b < 64; b++) s += g_part[b];
        double avg_m = s / (double)NPTS;
        double avg_Nx = 0.0;
        for (int c = 0; c < NCLS; c++) {
            double nx = (double)hist[c];
            avg_Nx += (nx / (double)NPTS) * digamma_d(nx);
        }
        double mi = (digamma_d((double)NPTS) - avg_Nx
                   + digamma_d((double)KNN) - avg_m) / log(2.0);
        if (mi < 0.0) mi = 0.0;
        out[0] = (float)mi;
    }
}

// ---------------- launch ----------------
extern "C" void kernel_launch(void* const* d_in, const int* in_sizes, int n_in,
                              void* d_out, int out_size) {
    const float* X = (const float*)d_in[0];
    const int*   y = (const int*)d_in[1];
    float* out = (float*)d_out;
    (void)in_sizes; (void)n_in; (void)out_size;

    cudaFuncSetAttribute(gemm_kernel, cudaFuncAttributeMaxDynamicSharedMemorySize, GSMEM);

    prep_kernel<<<NPTS / 8, 256>>>(X);
    gemm_kernel<<<NTRI, 256, GSMEM>>>(y);
    anchor_kernel<<<NPTS / 8, 256>>>();
    count_kernel<<<NPTS / 8, 256>>>();
    fin_part_kernel<<<64, 128>>>();
    fin2_kernel<<<1, 256>>>(y, out);
}

// round 5
// speedup vs baseline: 1.6019x; 1.6019x over previous
#include <cuda_runtime.h>
#include <cuda_bf16.h>
#include <cstdint>
#include <math.h>

#define NPTS 8192
#define DIM  256
#define NCLS 10
#define KNN  3
#define NT   64          // 8192/128 tiles per dim (full matrix)
#define NTRI (NT*(NT+1)/2)
#define NTC  8           // max class tiles per dim (max class size < 1024)
#define CTRI (NTC*(NTC+1)/2)   // 36

// ---------------- device scratch ----------------
__device__ float g_sq[NPTS];
__device__ int   g_cnt[NPTS];
__device__ float g_anchor[NPTS];
__device__ float4 g_top4[(size_t)NPTS * NTC];        // per-(row, class-tile) sorted-4 (512 KB)
__device__ double g_part[64];
__device__ __nv_bfloat16 g_Xhi[(size_t)NPTS * DIM];  // 4 MB
__device__ __nv_bfloat16 g_Xlo[(size_t)NPTS * DIM];  // 4 MB
__device__ int g_perm[NPTS];
__device__ int g_cbase[NCLS];
__device__ int g_ccnt[NCLS];

// ---------------- helpers ----------------
__device__ __forceinline__ uint32_t smem_u32(const void* p) {
    uint32_t a;
    asm("{ .reg .u64 t; cvta.to.shared.u64 t, %1; cvt.u32.u64 %0, t; }" : "=r"(a) : "l"(p));
    return a;
}
__device__ __forceinline__ void cp16(uint32_t dst, const void* src) {
    asm volatile("cp.async.cg.shared.global [%0], [%1], 16;" :: "r"(dst), "l"(src));
}
#define CP_COMMIT() asm volatile("cp.async.commit_group;" ::: "memory")
#define CP_WAIT0()  asm volatile("cp.async.wait_group 0;" ::: "memory")

#define MMA16816(d, a, b) \
  asm volatile("mma.sync.aligned.m16n8k16.row.col.f32.bf16.bf16.f32 " \
      "{%0,%1,%2,%3}, {%4,%5,%6,%7}, {%8,%9}, {%0,%1,%2,%3};" \
      : "+f"(d[0]), "+f"(d[1]), "+f"(d[2]), "+f"(d[3]) \
      : "r"(a[0]), "r"(a[1]), "r"(a[2]), "r"(a[3]), "r"(b[0]), "r"(b[1]))

__device__ __forceinline__ void ins4(float v, float& b0, float& b1, float& b2, float& b3) {
    if (v < b3) {
        if (v < b2) {
            b3 = b2;
            if (v < b1) {
                b2 = b1;
                if (v < b0) { b1 = b0; b0 = v; } else b1 = v;
            } else b2 = v;
        } else b3 = v;
    }
}
__device__ __forceinline__ void merge_sorted4(float* a, const float* b) {
    float r0, r1, r2, r3;
    int i = 0, j = 0;
    r0 = (a[0] <= b[0]) ? a[i++] : b[j++];
    r1 = (a[i] <= b[j]) ? a[i++] : b[j++];
    r2 = (a[i] <= b[j]) ? a[i++] : b[j++];
    r3 = (a[i] <= b[j]) ? a[i++] : b[j++];
    a[0] = r0; a[1] = r1; a[2] = r2; a[3] = r3;
}

// ---------------- kernel 1: split X, norms, init top4/cnt ----------------
__global__ void __launch_bounds__(256) prep_kernel(const float* __restrict__ X) {
    int row  = blockIdx.x * 8 + (threadIdx.x >> 5);
    int lane = threadIdx.x & 31;
    const float* xr = X + (size_t)row * DIM + lane * 8;
    float4 v0 = *(const float4*)xr;
    float4 v1 = *(const float4*)(xr + 4);
    float v[8] = {v0.x, v0.y, v0.z, v0.w, v1.x, v1.y, v1.z, v1.w};
    uint32_t ph[4], pl[4];
    float s = 0.f;
    #pragma unroll
    for (int q = 0; q < 4; q++) {
        float a = v[2 * q], b = v[2 * q + 1];
        __nv_bfloat16 ha = __float2bfloat16(a), hb = __float2bfloat16(b);
        __nv_bfloat16 la = __float2bfloat16(a - __bfloat162float(ha));
        __nv_bfloat16 lb = __float2bfloat16(b - __bfloat162float(hb));
        ph[q] = ((uint32_t)__bfloat16_as_ushort(hb) << 16) | __bfloat16_as_ushort(ha);
        pl[q] = ((uint32_t)__bfloat16_as_ushort(lb) << 16) | __bfloat16_as_ushort(la);
        s = fmaf(a, a, fmaf(b, b, s));
    }
    size_t off = (size_t)row * DIM + lane * 8;
    *(uint4*)(g_Xhi + off) = make_uint4(ph[0], ph[1], ph[2], ph[3]);
    *(uint4*)(g_Xlo + off) = make_uint4(pl[0], pl[1], pl[2], pl[3]);
    #pragma unroll
    for (int o = 16; o; o >>= 1) s += __shfl_xor_sync(0xffffffffu, s, o);
    if (lane == 0) g_sq[row] = s;
    if (lane < NTC) g_top4[(size_t)row * NTC + lane] =
        make_float4(INFINITY, INFINITY, INFINITY, INFINITY);
    if (lane == 8) g_cnt[row] = 0;
}

// ---------------- kernel 1b: class permutation ----------------
__global__ void perm_kernel(const int* __restrict__ y) {
    __shared__ int cnt[NCLS], base[NCLS];
    const int tid = threadIdx.x;
    if (tid < NCLS) cnt[tid] = 0;
    __syncthreads();
    for (int i = tid; i < NPTS; i += 1024) atomicAdd(&cnt[y[i]], 1);
    __syncthreads();
    if (tid == 0) {
        int b = 0;
        for (int c = 0; c < NCLS; c++) {
            base[c] = b; g_cbase[c] = b; g_ccnt[c] = cnt[c]; b += cnt[c];
        }
    }
    __syncthreads();
    if (tid < NCLS) cnt[tid] = 0;
    __syncthreads();
    for (int i = tid; i < NPTS; i += 1024) {
        int c = y[i];
        int pos = base[c] + atomicAdd(&cnt[c], 1);
        g_perm[pos] = i;
    }
}

// ---------------- shared GEMM config ----------------
#define TPITCH   80
#define TILE_SB  (128 * TPITCH)
#define STAGE_SB (4 * TILE_SB)
#define BUFPITCH 132
#define S4OFF    (128 * BUFPITCH * 4)
#define GSMEM    (2 * STAGE_SB)          // 81920 B

// ---------------- kernel 2: phase A — class-grouped GEMM -> top-4 partials ---------
__global__ void __launch_bounds__(256) classA_kernel() {
    extern __shared__ char smem[];
    __shared__ int pr[128], pc[128];
    const int tid = threadIdx.x, wid = tid >> 5, lane = tid & 31;
    const int warp_m = wid >> 2, warp_n = wid & 3;

    const int cls = blockIdx.x / CTRI;
    int t = blockIdx.x % CTRI;
    int ti = 0;
    while (t >= NTC - ti) { t -= NTC - ti; ti++; }
    const int tj = ti + t;
    const int nc = g_ccnt[cls];
    const int ntc = (nc + 127) >> 7;
    if (tj >= ntc) return;
    const int base = g_cbase[cls];

    if (tid < 128) {
        int p = ti * 128 + tid;
        pr[tid] = g_perm[base + min(p, nc - 1)];
    } else {
        int p = tj * 128 + (tid - 128);
        pc[tid - 128] = g_perm[base + min(p, nc - 1)];
    }
    __syncthreads();

    const uint32_t sb = smem_u32(smem);

    auto load_stage = [&](int stage, int kc) {
        uint32_t bA = sb + stage * STAGE_SB;
        #pragma unroll
        for (int i = 0; i < 8; i++) {
            int gid = tid + i * 256;
            int tile = gid >> 9, rem = gid & 511;
            int r = rem >> 2, c = rem & 3;
            int grow = (tile < 2) ? pr[r] : pc[r];
            const __nv_bfloat16* src = ((tile & 1) ? g_Xlo : g_Xhi)
                                     + (size_t)grow * DIM + kc * 32 + c * 8;
            cp16(bA + tile * TILE_SB + r * TPITCH + c * 16, src);
        }
        CP_COMMIT();
    };

    float acc[4][4][4];
    #pragma unroll
    for (int mt = 0; mt < 4; mt++)
        #pragma unroll
        for (int nt = 0; nt < 4; nt++)
            #pragma unroll
            for (int e = 0; e < 4; e++) acc[mt][nt][e] = 0.f;

    load_stage(0, 0);
    CP_WAIT0(); __syncthreads();

    const int frag_r = lane >> 2, frag_k = lane & 3;

    #pragma unroll 1
    for (int kc = 0; kc < 8; kc++) {
        if (kc < 7) load_stage((kc + 1) & 1, kc + 1);
        const char* st = smem + (kc & 1) * STAGE_SB;
        #pragma unroll
        for (int ks = 0; ks < 2; ks++) {
            uint32_t ah[4][4], al[4][4], bh[4][2], bl[4][2];
            #pragma unroll
            for (int mt = 0; mt < 4; mt++) {
                int r = warp_m * 64 + mt * 16 + frag_r;
                const char* pa = st + r * TPITCH + ks * 32 + frag_k * 4;
                ah[mt][0] = *(const uint32_t*)(pa);
                ah[mt][1] = *(const uint32_t*)(pa + 8 * TPITCH);
                ah[mt][2] = *(const uint32_t*)(pa + 16);
                ah[mt][3] = *(const uint32_t*)(pa + 8 * TPITCH + 16);
                const char* pl2 = pa + TILE_SB;
                al[mt][0] = *(const uint32_t*)(pl2);
                al[mt][1] = *(const uint32_t*)(pl2 + 8 * TPITCH);
                al[mt][2] = *(const uint32_t*)(pl2 + 16);
                al[mt][3] = *(const uint32_t*)(pl2 + 8 * TPITCH + 16);
            }
            #pragma unroll
            for (int nt = 0; nt < 4; nt++) {
                int n = warp_n * 32 + nt * 8 + frag_r;
                const char* pb = st + 2 * TILE_SB + n * TPITCH + ks * 32 + frag_k * 4;
                bh[nt][0] = *(const uint32_t*)(pb);
                bh[nt][1] = *(const uint32_t*)(pb + 16);
                bl[nt][0] = *(const uint32_t*)(pb + TILE_SB);
                bl[nt][1] = *(const uint32_t*)(pb + TILE_SB + 16);
            }
            #pragma unroll
            for (int mt = 0; mt < 4; mt++)
                #pragma unroll
                for (int nt = 0; nt < 4; nt++) {
                    MMA16816(acc[mt][nt], ah[mt], bh[nt]);
                    MMA16816(acc[mt][nt], ah[mt], bl[nt]);
                    MMA16816(acc[mt][nt], al[mt], bh[nt]);
                }
        }
        if (kc < 7) { CP_WAIT0(); __syncthreads(); }
    }
    __syncthreads();

    float sqi[8], sqj[8];
    #pragma unroll
    for (int mt = 0; mt < 4; mt++) {
        sqi[2 * mt]     = g_sq[pr[warp_m * 64 + mt * 16 + frag_r]];
        sqi[2 * mt + 1] = g_sq[pr[warp_m * 64 + mt * 16 + frag_r + 8]];
    }
    #pragma unroll
    for (int nt = 0; nt < 4; nt++) {
        sqj[2 * nt]     = g_sq[pc[warp_n * 32 + nt * 8 + 2 * frag_k]];
        sqj[2 * nt + 1] = g_sq[pc[warp_n * 32 + nt * 8 + 2 * frag_k + 1]];
    }

    float* buf = (float*)smem;
    #pragma unroll
    for (int mt = 0; mt < 4; mt++) {
        int r0 = warp_m * 64 + mt * 16 + frag_r;
        #pragma unroll
        for (int nt = 0; nt < 4; nt++) {
            int c0 = warp_n * 32 + nt * 8 + 2 * frag_k;
            buf[r0 * BUFPITCH + c0]           = fmaxf(fmaf(-2.f, acc[mt][nt][0], sqi[2*mt]   + sqj[2*nt]),   0.f);
            buf[r0 * BUFPITCH + c0 + 1]       = fmaxf(fmaf(-2.f, acc[mt][nt][1], sqi[2*mt]   + sqj[2*nt+1]), 0.f);
            buf[(r0 + 8) * BUFPITCH + c0]     = fmaxf(fmaf(-2.f, acc[mt][nt][2], sqi[2*mt+1] + sqj[2*nt]),   0.f);
            buf[(r0 + 8) * BUFPITCH + c0 + 1] = fmaxf(fmaf(-2.f, acc[mt][nt][3], sqi[2*mt+1] + sqj[2*nt+1]), 0.f);
        }
    }
    __syncthreads();

    float4* s4 = (float4*)(smem + S4OFF);
    const int rowlim = nc - ti * 128;   // valid rows in this tile
    const int collim = nc - tj * 128;   // valid cols

    // straight top-4: 2 threads per row
    {
        int r = tid >> 1, h = tid & 1;
        const float* br = buf + r * BUFPITCH + h * 64;
        float b0 = INFINITY, b1 = INFINITY, b2 = INFINITY, b3 = INFINITY;
        int lim = min(64, collim - h * 64);
        for (int s = 0; s < lim; s++) ins4(br[s], b0, b1, b2, b3);
        s4[tid] = make_float4(b0, b1, b2, b3);
    }
    __syncthreads();
    if ((tid & 1) == 0) {
        int r = tid >> 1;
        if (r < rowlim) {
            float a[4] = {s4[tid].x, s4[tid].y, s4[tid].z, s4[tid].w};
            float b[4] = {s4[tid + 1].x, s4[tid + 1].y, s4[tid + 1].z, s4[tid + 1].w};
            merge_sorted4(a, b);
            g_top4[(size_t)pr[r] * NTC + tj] = make_float4(a[0], a[1], a[2], a[3]);
        }
    }

    if (ti != tj) {
        __syncthreads();
        {
            int c = tid >> 1, h = tid & 1;
            float b0 = INFINITY, b1 = INFINITY, b2 = INFINITY, b3 = INFINITY;
            int lim = min(64, rowlim - h * 64);
            for (int s = 0; s < lim; s++)
                ins4(buf[(h * 64 + s) * BUFPITCH + c], b0, b1, b2, b3);
            s4[tid] = make_float4(b0, b1, b2, b3);
        }
        __syncthreads();
        if ((tid & 1) == 0) {
            int c = tid >> 1;
            if (c < collim) {
                float a[4] = {s4[tid].x, s4[tid].y, s4[tid].z, s4[tid].w};
                float b[4] = {s4[tid + 1].x, s4[tid + 1].y, s4[tid + 1].z, s4[tid + 1].w};
                merge_sorted4(a, b);
                g_top4[(size_t)pc[c] * NTC + ti] = make_float4(a[0], a[1], a[2], a[3]);
            }
        }
    }
}

// ---------------- kernel 3: anchor reduce (warp per row) ----------------
__global__ void __launch_bounds__(256) anchor_kernel() {
    const int tid = threadIdx.x, wid = tid >> 5, lane = tid & 31;
    const int row = blockIdx.x * 8 + wid;
    float q[4] = {INFINITY, INFINITY, INFINITY, INFINITY};
    if (lane < NTC) {
        float4 v = g_top4[(size_t)row * NTC + lane];
        q[0] = v.x; q[1] = v.y; q[2] = v.z; q[3] = v.w;
    }
    #pragma unroll
    for (int off = 16; off; off >>= 1) {
        float o[4];
        #pragma unroll
        for (int e = 0; e < 4; e++) o[e] = __shfl_xor_sync(0xffffffffu, q[e], off);
        merge_sorted4(q, o);
    }
    if (lane == 0) g_anchor[row] = q[3];
}

// ---------------- kernel 4: phase B — full symmetric GEMM, fused count -------------
__global__ void __launch_bounds__(256) gemmB_kernel() {
    extern __shared__ char smem[];
    __shared__ float s_anc[256];
    __shared__ int scnt[256];
    const int tid = threadIdx.x, wid = tid >> 5, lane = tid & 31;
    const int warp_m = wid >> 2, warp_n = wid & 3;

    int idx = blockIdx.x;
    int bi = (int)((2 * NT + 1 - sqrtf((float)((2 * NT + 1) * (2 * NT + 1) - 8 * idx))) * 0.5f);
    while ((bi + 1) * NT - ((bi + 1) * bi) / 2 <= idx) bi++;
    while (bi * NT - (bi * (bi - 1)) / 2 > idx) bi--;
    int bj = bi + (idx - (bi * NT - (bi * (bi - 1)) / 2));
    const int row0 = bi * 128, col0 = bj * 128;

    if (tid < 128) s_anc[tid] = g_anchor[row0 + tid];
    else           s_anc[tid] = g_anchor[col0 + tid - 128];
    scnt[tid] = 0;

    const __nv_bfloat16* srcs[4] = {
        g_Xhi + (size_t)row0 * DIM, g_Xlo + (size_t)row0 * DIM,
        g_Xhi + (size_t)col0 * DIM, g_Xlo + (size_t)col0 * DIM };

    const uint32_t sb = smem_u32(smem);

    auto load_stage = [&](int stage, int kc) {
        uint32_t bA = sb + stage * STAGE_SB;
        #pragma unroll
        for (int i = 0; i < 8; i++) {
            int gid = tid + i * 256;
            int tile = gid >> 9, rem = gid & 511;
            int r = rem >> 2, c = rem & 3;
            cp16(bA + tile * TILE_SB + r * TPITCH + c * 16,
                 srcs[tile] + (size_t)r * DIM + kc * 32 + c * 8);
        }
        CP_COMMIT();
    };

    float acc[4][4][4];
    #pragma unroll
    for (int mt = 0; mt < 4; mt++)
        #pragma unroll
        for (int nt = 0; nt < 4; nt++)
            #pragma unroll
            for (int e = 0; e < 4; e++) acc[mt][nt][e] = 0.f;

    load_stage(0, 0);
    CP_WAIT0(); __syncthreads();

    const int frag_r = lane >> 2, frag_k = lane & 3;

    #pragma unroll 1
    for (int kc = 0; kc < 8; kc++) {
        if (kc < 7) load_stage((kc + 1) & 1, kc + 1);
        const char* st = smem + (kc & 1) * STAGE_SB;
        #pragma unroll
        for (int ks = 0; ks < 2; ks++) {
            uint32_t ah[4][4], al[4][4], bh[4][2], bl[4][2];
            #pragma unroll
            for (int mt = 0; mt < 4; mt++) {
                int r = warp_m * 64 + mt * 16 + frag_r;
                const char* pa = st + r * TPITCH + ks * 32 + frag_k * 4;
                ah[mt][0] = *(const uint32_t*)(pa);
                ah[mt][1] = *(const uint32_t*)(pa + 8 * TPITCH);
                ah[mt][2] = *(const uint32_t*)(pa + 16);
                ah[mt][3] = *(const uint32_t*)(pa + 8 * TPITCH + 16);
                const char* pl2 = pa + TILE_SB;
                al[mt][0] = *(const uint32_t*)(pl2);
                al[mt][1] = *(const uint32_t*)(pl2 + 8 * TPITCH);
                al[mt][2] = *(const uint32_t*)(pl2 + 16);
                al[mt][3] = *(const uint32_t*)(pl2 + 8 * TPITCH + 16);
            }
            #pragma unroll
            for (int nt = 0; nt < 4; nt++) {
                int n = warp_n * 32 + nt * 8 + frag_r;
                const char* pb = st + 2 * TILE_SB + n * TPITCH + ks * 32 + frag_k * 4;
                bh[nt][0] = *(const uint32_t*)(pb);
                bh[nt][1] = *(const uint32_t*)(pb + 16);
                bl[nt][0] = *(const uint32_t*)(pb + TILE_SB);
                bl[nt][1] = *(const uint32_t*)(pb + TILE_SB + 16);
            }
            #pragma unroll
            for (int mt = 0; mt < 4; mt++)
                #pragma unroll
                for (int nt = 0; nt < 4; nt++) {
                    MMA16816(acc[mt][nt], ah[mt], bh[nt]);
                    MMA16816(acc[mt][nt], ah[mt], bl[nt]);
                    MMA16816(acc[mt][nt], al[mt], bh[nt]);
                }
        }
        if (kc < 7) { CP_WAIT0(); __syncthreads(); }
    }

    // epilogue: register-resident count vs anchors
    float sqi[8], sqj[8], ar[8], ac[8];
    #pragma unroll
    for (int mt = 0; mt < 4; mt++) {
        int r = warp_m * 64 + mt * 16 + frag_r;
        sqi[2 * mt] = g_sq[row0 + r];       sqi[2 * mt + 1] = g_sq[row0 + r + 8];
        ar[2 * mt]  = s_anc[r];             ar[2 * mt + 1]  = s_anc[r + 8];
    }
    #pragma unroll
    for (int nt = 0; nt < 4; nt++) {
        int c = warp_n * 32 + nt * 8 + 2 * frag_k;
        sqj[2 * nt] = g_sq[col0 + c];       sqj[2 * nt + 1] = g_sq[col0 + c + 1];
        ac[2 * nt]  = s_anc[128 + c];       ac[2 * nt + 1]  = s_anc[128 + c + 1];
    }

    int rc[8] = {0,0,0,0,0,0,0,0}, cc[8] = {0,0,0,0,0,0,0,0};
    #pragma unroll
    for (int mt = 0; mt < 4; mt++)
        #pragma unroll
        for (int nt = 0; nt < 4; nt++) {
            float d00 = fmaxf(fmaf(-2.f, acc[mt][nt][0], sqi[2*mt]   + sqj[2*nt]),   0.f);
            float d01 = fmaxf(fmaf(-2.f, acc[mt][nt][1], sqi[2*mt]   + sqj[2*nt+1]), 0.f);
            float d10 = fmaxf(fmaf(-2.f, acc[mt][nt][2], sqi[2*mt+1] + sqj[2*nt]),   0.f);
            float d11 = fmaxf(fmaf(-2.f, acc[mt][nt][3], sqi[2*mt+1] + sqj[2*nt+1]), 0.f);
            rc[2*mt]   += (d00 < ar[2*mt])   + (d01 < ar[2*mt]);
            rc[2*mt+1] += (d10 < ar[2*mt+1]) + (d11 < ar[2*mt+1]);
            cc[2*nt]   += (d00 < ac[2*nt])   + (d10 < ac[2*nt]);
            cc[2*nt+1] += (d01 < ac[2*nt+1]) + (d11 < ac[2*nt+1]);
        }

    __syncthreads();   // scnt zeros + all reads of s_anc done
    #pragma unroll
    for (int mt = 0; mt < 4; mt++) {
        int r = warp_m * 64 + mt * 16 + frag_r;
        atomicAdd(&scnt[r], rc[2 * mt]);
        atomicAdd(&scnt[r + 8], rc[2 * mt + 1]);
    }
    if (bi != bj) {
        #pragma unroll
        for (int nt = 0; nt < 4; nt++) {
            int c = warp_n * 32 + nt * 8 + 2 * frag_k;
            atomicAdd(&scnt[128 + c], cc[2 * nt]);
            atomicAdd(&scnt[128 + c + 1], cc[2 * nt + 1]);
        }
    }
    __syncthreads();
    if (tid < 128) atomicAdd(&g_cnt[row0 + tid], scnt[tid]);
    else if (bi != bj) atomicAdd(&g_cnt[col0 + tid - 128], scnt[tid]);
}

// ---------------- kernel 5: finalize ----------------
__device__ double digamma_d(double x) {
    double r = 0.0;
    while (x < 6.0) { r -= 1.0 / x; x += 1.0; }
    double f = 1.0 / (x * x);
    double ser = f * (1.0 / 12.0 - f * (1.0 / 120.0 - f * (1.0 / 252.0
               - f * (1.0 / 240.0 - f * (1.0 / 132.0)))));
    return r + log(x) - 0.5 / x - ser;
}

__global__ void fin_part_kernel() {
    __shared__ double sd[128];
    const int tid = threadIdx.x;
    int r = blockIdx.x * 128 + tid;
    float arg = (float)(g_cnt[r] - 1) + 1e-7f;   // m_i = count - 1 (self)
    sd[tid] = digamma_d((double)arg);
    __syncthreads();
    for (int off = 64; off; off >>= 1) {
        if (tid < off) sd[tid] += sd[tid + off];
        __syncthreads();
    }
    if (tid == 0) g_part[blockIdx.x] = sd[0];
}

__global__ void fin2_kernel(const int* __restrict__ y, float* __restrict__ out) {
    __shared__ int hist[NCLS];
    const int tid = threadIdx.x;
    if (tid < NCLS) hist[tid] = 0;
    __syncthreads();
    for (int j = tid; j < NPTS; j += 256) atomicAdd(&hist[y[j]], 1);
    __syncthreads();
    if (tid == 0) {
        double s = 0.0;
        for (int b = 0; b < 64; b++) s += g_part[b];
        double avg_m = s / (double)NPTS;
        double avg_Nx = 0.0;
        for (int c = 0; c < NCLS; c++) {
            double nx = (double)hist[c];
            avg_Nx += (nx / (double)NPTS) * digamma_d(nx);
        }
        double mi = (digamma_d((double)NPTS) - avg_Nx
                   + digamma_d((double)KNN) - avg_m) / log(2.0);
        if (mi < 0.0) mi = 0.0;
        out[0] = (float)mi;
    }
}

// ---------------- launch ----------------
extern "C" void kernel_launch(void* const* d_in, const int* in_sizes, int n_in,
                              void* d_out, int out_size) {
    const float* X = (const float*)d_in[0];
    const int*   y = (const int*)d_in[1];
    float* out = (float*)d_out;
    (void)in_sizes; (void)n_in; (void)out_size;

    cudaFuncSetAttribute(classA_kernel, cudaFuncAttributeMaxDynamicSharedMemorySize, GSMEM);
    cudaFuncSetAttribute(gemmB_kernel,  cudaFuncAttributeMaxDynamicSharedMemorySize, GSMEM);

    prep_kernel<<<NPTS / 8, 256>>>(X);
    perm_kernel<<<1, 1024>>>(y);
    classA_kernel<<<NCLS * CTRI, 256, GSMEM>>>();
    anchor_kernel<<<NPTS / 8, 256>>>();
    gemmB_kernel<<<NTRI, 256, GSMEM>>>();
    fin_part_kernel<<<64, 128>>>();
    fin2_kernel<<<1, 256>>>(y, out);
}

// round 6
// speedup vs baseline: 1.6299x; 1.0175x over previous
#include <cuda_runtime.h>
#include <cuda_bf16.h>
#include <cstdint>
#include <math.h>

#define NPTS 8192
#define DIM  256
#define NCLS 10
#define KNN  3
#define NT   64
#define NTRI (NT*(NT+1)/2)
#define NTC  8
#define CTRI (NTC*(NTC+1)/2)

// ---------------- device scratch ----------------
__device__ float g_sq[NPTS];
__device__ int   g_cnt[NPTS];
__device__ float g_anchor[NPTS];
__device__ float4 g_top4[(size_t)NPTS * NTC];
__device__ double g_part[64];
__device__ __nv_bfloat16 g_Xhi[(size_t)NPTS * DIM];
__device__ __nv_bfloat16 g_Xlo[(size_t)NPTS * DIM];
__device__ int g_perm[NPTS];
__device__ int g_cbase[NCLS];
__device__ int g_ccnt[NCLS];

// ---------------- helpers ----------------
__device__ __forceinline__ uint32_t smem_u32(const void* p) {
    uint32_t a;
    asm("{ .reg .u64 t; cvta.to.shared.u64 t, %1; cvt.u32.u64 %0, t; }" : "=r"(a) : "l"(p));
    return a;
}
__device__ __forceinline__ void cp16(uint32_t dst, const void* src) {
    asm volatile("cp.async.cg.shared.global [%0], [%1], 16;" :: "r"(dst), "l"(src));
}
#define CP_COMMIT() asm volatile("cp.async.commit_group;" ::: "memory")
#define CP_WAIT0()  asm volatile("cp.async.wait_group 0;" ::: "memory")

#define MMA16816(d, a, b) \
  asm volatile("mma.sync.aligned.m16n8k16.row.col.f32.bf16.bf16.f32 " \
      "{%0,%1,%2,%3}, {%4,%5,%6,%7}, {%8,%9}, {%0,%1,%2,%3};" \
      : "+f"(d[0]), "+f"(d[1]), "+f"(d[2]), "+f"(d[3]) \
      : "r"(a[0]), "r"(a[1]), "r"(a[2]), "r"(a[3]), "r"(b[0]), "r"(b[1]))

__device__ __forceinline__ void ldsm_x4(uint32_t* r, uint32_t addr) {
    asm volatile("ldmatrix.sync.aligned.m8n8.x4.shared.b16 {%0,%1,%2,%3}, [%4];"
        : "=r"(r[0]), "=r"(r[1]), "=r"(r[2]), "=r"(r[3]) : "r"(addr));
}

__device__ __forceinline__ void ins4(float v, float& b0, float& b1, float& b2, float& b3) {
    if (v < b3) {
        if (v < b2) {
            b3 = b2;
            if (v < b1) {
                b2 = b1;
                if (v < b0) { b1 = b0; b0 = v; } else b1 = v;
            } else b2 = v;
        } else b3 = v;
    }
}
__device__ __forceinline__ void merge_sorted4(float* a, const float* b) {
    float r0, r1, r2, r3;
    int i = 0, j = 0;
    r0 = (a[0] <= b[0]) ? a[i++] : b[j++];
    r1 = (a[i] <= b[j]) ? a[i++] : b[j++];
    r2 = (a[i] <= b[j]) ? a[i++] : b[j++];
    r3 = (a[i] <= b[j]) ? a[i++] : b[j++];
    a[0] = r0; a[1] = r1; a[2] = r2; a[3] = r3;
}

// ---------------- kernel 1: split X, norms, init ----------------
__global__ void __launch_bounds__(256) prep_kernel(const float* __restrict__ X) {
    int row  = blockIdx.x * 8 + (threadIdx.x >> 5);
    int lane = threadIdx.x & 31;
    const float* xr = X + (size_t)row * DIM + lane * 8;
    float4 v0 = *(const float4*)xr;
    float4 v1 = *(const float4*)(xr + 4);
    float v[8] = {v0.x, v0.y, v0.z, v0.w, v1.x, v1.y, v1.z, v1.w};
    uint32_t ph[4], pl[4];
    float s = 0.f;
    #pragma unroll
    for (int q = 0; q < 4; q++) {
        float a = v[2 * q], b = v[2 * q + 1];
        __nv_bfloat16 ha = __float2bfloat16(a), hb = __float2bfloat16(b);
        __nv_bfloat16 la = __float2bfloat16(a - __bfloat162float(ha));
        __nv_bfloat16 lb = __float2bfloat16(b - __bfloat162float(hb));
        ph[q] = ((uint32_t)__bfloat16_as_ushort(hb) << 16) | __bfloat16_as_ushort(ha);
        pl[q] = ((uint32_t)__bfloat16_as_ushort(lb) << 16) | __bfloat16_as_ushort(la);
        s = fmaf(a, a, fmaf(b, b, s));
    }
    size_t off = (size_t)row * DIM + lane * 8;
    *(uint4*)(g_Xhi + off) = make_uint4(ph[0], ph[1], ph[2], ph[3]);
    *(uint4*)(g_Xlo + off) = make_uint4(pl[0], pl[1], pl[2], pl[3]);
    #pragma unroll
    for (int o = 16; o; o >>= 1) s += __shfl_xor_sync(0xffffffffu, s, o);
    if (lane == 0) g_sq[row] = s;
    if (lane < NTC) g_top4[(size_t)row * NTC + lane] =
        make_float4(INFINITY, INFINITY, INFINITY, INFINITY);
    if (lane == 8) g_cnt[row] = 0;
}

// ---------------- kernel 1b: class permutation ----------------
__global__ void perm_kernel(const int* __restrict__ y) {
    __shared__ int cnt[NCLS], base[NCLS];
    const int tid = threadIdx.x;
    if (tid < NCLS) cnt[tid] = 0;
    __syncthreads();
    for (int i = tid; i < NPTS; i += 1024) atomicAdd(&cnt[y[i]], 1);
    __syncthreads();
    if (tid == 0) {
        int b = 0;
        for (int c = 0; c < NCLS; c++) {
            base[c] = b; g_cbase[c] = b; g_ccnt[c] = cnt[c]; b += cnt[c];
        }
    }
    __syncthreads();
    if (tid < NCLS) cnt[tid] = 0;
    __syncthreads();
    for (int i = tid; i < NPTS; i += 1024) {
        int c = y[i];
        int pos = base[c] + atomicAdd(&cnt[c], 1);
        g_perm[pos] = i;
    }
}

// ---------------- shared GEMM config ----------------
#define TPITCH   80
#define TILE_SB  (128 * TPITCH)
#define STAGE_SB (4 * TILE_SB)
#define BUFPITCH 132
#define S4OFF    (128 * BUFPITCH * 4)
#define GSMEM    (2 * STAGE_SB)

// mainloop macro: ldmatrix fragment loads + 96 MMAs per kc
#define GEMM_MAINLOOP(LOAD_STAGE)                                              \
    LOAD_STAGE(0, 0);                                                          \
    CP_WAIT0(); __syncthreads();                                               \
    _Pragma("unroll 1")                                                        \
    for (int kc = 0; kc < 8; kc++) {                                           \
        if (kc < 7) LOAD_STAGE((kc + 1) & 1, kc + 1);                          \
        const uint32_t st = sb + (kc & 1) * STAGE_SB;                          \
        _Pragma("unroll")                                                      \
        for (int ks = 0; ks < 2; ks++) {                                       \
            uint32_t ah[4][4], al[4][4], bh[4][2], bl[4][2];                   \
            const uint32_t a_l16 = lane & 15, a_hi16 = (lane >> 4) * 16;       \
            _Pragma("unroll")                                                  \
            for (int mt = 0; mt < 4; mt++) {                                   \
                uint32_t rowa = warp_m * 64 + mt * 16 + a_l16;                 \
                uint32_t ad = st + rowa * TPITCH + ks * 32 + a_hi16;           \
                ldsm_x4(ah[mt], ad);                                           \
                ldsm_x4(al[mt], ad + TILE_SB);                                 \
            }                                                                  \
            const uint32_t g = lane >> 3;                                      \
            const uint32_t b_boff = (g & 1) * 16;                              \
            _Pragma("unroll")                                                  \
            for (int np = 0; np < 2; np++) {                                   \
                uint32_t rown = warp_n * 32 + np * 16 + (g >> 1) * 8 + (lane & 7); \
                uint32_t bd = st + 2 * TILE_SB + rown * TPITCH + ks * 32 + b_boff; \
                uint32_t tb[4];                                                \
                ldsm_x4(tb, bd);                                               \
                bh[2*np][0] = tb[0]; bh[2*np][1] = tb[1];                      \
                bh[2*np+1][0] = tb[2]; bh[2*np+1][1] = tb[3];                  \
                ldsm_x4(tb, bd + TILE_SB);                                     \
                bl[2*np][0] = tb[0]; bl[2*np][1] = tb[1];                      \
                bl[2*np+1][0] = tb[2]; bl[2*np+1][1] = tb[3];                  \
            }                                                                  \
            _Pragma("unroll")                                                  \
            for (int mt = 0; mt < 4; mt++)                                     \
                _Pragma("unroll")                                              \
                for (int nt = 0; nt < 4; nt++) {                               \
                    MMA16816(acc[mt][nt], ah[mt], bh[nt]);                     \
                    MMA16816(acc[mt][nt], ah[mt], bl[nt]);                     \
                    MMA16816(acc[mt][nt], al[mt], bh[nt]);                     \
                }                                                              \
        }                                                                      \
        if (kc < 7) { CP_WAIT0(); __syncthreads(); }                           \
    }

// ---------------- kernel 2: phase A — class-grouped GEMM -> top-4 partials ---------
__global__ void __launch_bounds__(256) classA_kernel() {
    extern __shared__ char smem[];
    __shared__ int pr[128], pc[128];
    const int tid = threadIdx.x, wid = tid >> 5, lane = tid & 31;
    const int warp_m = wid >> 2, warp_n = wid & 3;

    const int cls = blockIdx.x / CTRI;
    int t = blockIdx.x % CTRI;
    int ti = 0;
    while (t >= NTC - ti) { t -= NTC - ti; ti++; }
    const int tj = ti + t;
    const int nc = g_ccnt[cls];
    const int ntc = (nc + 127) >> 7;
    if (tj >= ntc) return;
    const int base = g_cbase[cls];

    if (tid < 128) {
        int p = ti * 128 + tid;
        pr[tid] = g_perm[base + min(p, nc - 1)];
    } else {
        int p = tj * 128 + (tid - 128);
        pc[tid - 128] = g_perm[base + min(p, nc - 1)];
    }
    __syncthreads();

    const uint32_t sb = smem_u32(smem);

    auto load_stage = [&](int stage, int kc) {
        uint32_t bA = sb + stage * STAGE_SB;
        #pragma unroll
        for (int i = 0; i < 8; i++) {
            int gid = tid + i * 256;
            int tile = gid >> 9, rem = gid & 511;
            int r = rem >> 2, c = rem & 3;
            int grow = (tile < 2) ? pr[r] : pc[r];
            const __nv_bfloat16* src = ((tile & 1) ? g_Xlo : g_Xhi)
                                     + (size_t)grow * DIM + kc * 32 + c * 8;
            cp16(bA + tile * TILE_SB + r * TPITCH + c * 16, src);
        }
        CP_COMMIT();
    };

    float acc[4][4][4];
    #pragma unroll
    for (int mt = 0; mt < 4; mt++)
        #pragma unroll
        for (int nt = 0; nt < 4; nt++)
            #pragma unroll
            for (int e = 0; e < 4; e++) acc[mt][nt][e] = 0.f;

    GEMM_MAINLOOP(load_stage)
    __syncthreads();

    const int frag_r = lane >> 2, frag_k = lane & 3;
    float sqi[8], sqj[8];
    #pragma unroll
    for (int mt = 0; mt < 4; mt++) {
        sqi[2 * mt]     = g_sq[pr[warp_m * 64 + mt * 16 + frag_r]];
        sqi[2 * mt + 1] = g_sq[pr[warp_m * 64 + mt * 16 + frag_r + 8]];
    }
    #pragma unroll
    for (int nt = 0; nt < 4; nt++) {
        sqj[2 * nt]     = g_sq[pc[warp_n * 32 + nt * 8 + 2 * frag_k]];
        sqj[2 * nt + 1] = g_sq[pc[warp_n * 32 + nt * 8 + 2 * frag_k + 1]];
    }

    float* buf = (float*)smem;
    #pragma unroll
    for (int mt = 0; mt < 4; mt++) {
        int r0 = warp_m * 64 + mt * 16 + frag_r;
        #pragma unroll
        for (int nt = 0; nt < 4; nt++) {
            int c0 = warp_n * 32 + nt * 8 + 2 * frag_k;
            buf[r0 * BUFPITCH + c0]           = fmaxf(fmaf(-2.f, acc[mt][nt][0], sqi[2*mt]   + sqj[2*nt]),   0.f);
            buf[r0 * BUFPITCH + c0 + 1]       = fmaxf(fmaf(-2.f, acc[mt][nt][1], sqi[2*mt]   + sqj[2*nt+1]), 0.f);
            buf[(r0 + 8) * BUFPITCH + c0]     = fmaxf(fmaf(-2.f, acc[mt][nt][2], sqi[2*mt+1] + sqj[2*nt]),   0.f);
            buf[(r0 + 8) * BUFPITCH + c0 + 1] = fmaxf(fmaf(-2.f, acc[mt][nt][3], sqi[2*mt+1] + sqj[2*nt+1]), 0.f);
        }
    }
    __syncthreads();

    float4* s4 = (float4*)(smem + S4OFF);
    const int rowlim = nc - ti * 128;
    const int collim = nc - tj * 128;

    {
        int r = tid >> 1, h = tid & 1;
        const float* br = buf + r * BUFPITCH + h * 64;
        float b0 = INFINITY, b1 = INFINITY, b2 = INFINITY, b3 = INFINITY;
        int lim = min(64, collim - h * 64);
        for (int s = 0; s < lim; s++) ins4(br[s], b0, b1, b2, b3);
        s4[tid] = make_float4(b0, b1, b2, b3);
    }
    __syncthreads();
    if ((tid & 1) == 0) {
        int r = tid >> 1;
        if (r < rowlim) {
            float a[4] = {s4[tid].x, s4[tid].y, s4[tid].z, s4[tid].w};
            float b[4] = {s4[tid + 1].x, s4[tid + 1].y, s4[tid + 1].z, s4[tid + 1].w};
            merge_sorted4(a, b);
            g_top4[(size_t)pr[r] * NTC + tj] = make_float4(a[0], a[1], a[2], a[3]);
        }
    }

    if (ti != tj) {
        __syncthreads();
        {
            int c = tid >> 1, h = tid & 1;
            float b0 = INFINITY, b1 = INFINITY, b2 = INFINITY, b3 = INFINITY;
            int lim = min(64, rowlim - h * 64);
            for (int s = 0; s < lim; s++)
                ins4(buf[(h * 64 + s) * BUFPITCH + c], b0, b1, b2, b3);
            s4[tid] = make_float4(b0, b1, b2, b3);
        }
        __syncthreads();
        if ((tid & 1) == 0) {
            int c = tid >> 1;
            if (c < collim) {
                float a[4] = {s4[tid].x, s4[tid].y, s4[tid].z, s4[tid].w};
                float b[4] = {s4[tid + 1].x, s4[tid + 1].y, s4[tid + 1].z, s4[tid + 1].w};
                merge_sorted4(a, b);
                g_top4[(size_t)pc[c] * NTC + ti] = make_float4(a[0], a[1], a[2], a[3]);
            }
        }
    }
}

// ---------------- kernel 3: anchor reduce ----------------
__global__ void __launch_bounds__(256) anchor_kernel() {
    const int tid = threadIdx.x, wid = tid >> 5, lane = tid & 31;
    const int row = blockIdx.x * 8 + wid;
    float q[4] = {INFINITY, INFINITY, INFINITY, INFINITY};
    if (lane < NTC) {
        float4 v = g_top4[(size_t)row * NTC + lane];
        q[0] = v.x; q[1] = v.y; q[2] = v.z; q[3] = v.w;
    }
    #pragma unroll
    for (int off = 16; off; off >>= 1) {
        float o[4];
        #pragma unroll
        for (int e = 0; e < 4; e++) o[e] = __shfl_xor_sync(0xffffffffu, q[e], off);
        merge_sorted4(q, o);
    }
    if (lane == 0) g_anchor[row] = q[3];
}

// ---------------- kernel 4: phase B — full symmetric GEMM, fused count -------------
__global__ void __launch_bounds__(256) gemmB_kernel() {
    extern __shared__ char smem[];
    __shared__ float s_anc[256];
    __shared__ int scnt[256];
    const int tid = threadIdx.x, wid = tid >> 5, lane = tid & 31;
    const int warp_m = wid >> 2, warp_n = wid & 3;

    int idx = blockIdx.x;
    int bi = (int)((2 * NT + 1 - sqrtf((float)((2 * NT + 1) * (2 * NT + 1) - 8 * idx))) * 0.5f);
    while ((bi + 1) * NT - ((bi + 1) * bi) / 2 <= idx) bi++;
    while (bi * NT - (bi * (bi - 1)) / 2 > idx) bi--;
    int bj = bi + (idx - (bi * NT - (bi * (bi - 1)) / 2));
    const int row0 = bi * 128, col0 = bj * 128;

    if (tid < 128) s_anc[tid] = g_anchor[row0 + tid];
    else           s_anc[tid] = g_anchor[col0 + tid - 128];
    scnt[tid] = 0;

    const __nv_bfloat16* srcs[4] = {
        g_Xhi + (size_t)row0 * DIM, g_Xlo + (size_t)row0 * DIM,
        g_Xhi + (size_t)col0 * DIM, g_Xlo + (size_t)col0 * DIM };

    const uint32_t sb = smem_u32(smem);

    auto load_stage = [&](int stage, int kc) {
        uint32_t bA = sb + stage * STAGE_SB;
        #pragma unroll
        for (int i = 0; i < 8; i++) {
            int gid = tid + i * 256;
            int tile = gid >> 9, rem = gid & 511;
            int r = rem >> 2, c = rem & 3;
            cp16(bA + tile * TILE_SB + r * TPITCH + c * 16,
                 srcs[tile] + (size_t)r * DIM + kc * 32 + c * 8);
        }
        CP_COMMIT();
    };

    float acc[4][4][4];
    #pragma unroll
    for (int mt = 0; mt < 4; mt++)
        #pragma unroll
        for (int nt = 0; nt < 4; nt++)
            #pragma unroll
            for (int e = 0; e < 4; e++) acc[mt][nt][e] = 0.f;

    GEMM_MAINLOOP(load_stage)

    const int frag_r = lane >> 2, frag_k = lane & 3;
    float sqi[8], sqj[8], ar[8], ac[8];
    #pragma unroll
    for (int mt = 0; mt < 4; mt++) {
        int r = warp_m * 64 + mt * 16 + frag_r;
        sqi[2 * mt] = g_sq[row0 + r];       sqi[2 * mt + 1] = g_sq[row0 + r + 8];
        ar[2 * mt]  = s_anc[r];             ar[2 * mt + 1]  = s_anc[r + 8];
    }
    #pragma unroll
    for (int nt = 0; nt < 4; nt++) {
        int c = warp_n * 32 + nt * 8 + 2 * frag_k;
        sqj[2 * nt] = g_sq[col0 + c];       sqj[2 * nt + 1] = g_sq[col0 + c + 1];
        ac[2 * nt]  = s_anc[128 + c];       ac[2 * nt + 1]  = s_anc[128 + c + 1];
    }

    int rc[8] = {0,0,0,0,0,0,0,0}, cc[8] = {0,0,0,0,0,0,0,0};
    #pragma unroll
    for (int mt = 0; mt < 4; mt++)
        #pragma unroll
        for (int nt = 0; nt < 4; nt++) {
            float d00 = fmaxf(fmaf(-2.f, acc[mt][nt][0], sqi[2*mt]   + sqj[2*nt]),   0.f);
            float d01 = fmaxf(fmaf(-2.f, acc[mt][nt][1], sqi[2*mt]   + sqj[2*nt+1]), 0.f);
            float d10 = fmaxf(fmaf(-2.f, acc[mt][nt][2], sqi[2*mt+1] + sqj[2*nt]),   0.f);
            float d11 = fmaxf(fmaf(-2.f, acc[mt][nt][3], sqi[2*mt+1] + sqj[2*nt+1]), 0.f);
            rc[2*mt]   += (d00 < ar[2*mt])   + (d01 < ar[2*mt]);
            rc[2*mt+1] += (d10 < ar[2*mt+1]) + (d11 < ar[2*mt+1]);
            cc[2*nt]   += (d00 < ac[2*nt])   + (d10 < ac[2*nt]);
            cc[2*nt+1] += (d01 < ac[2*nt+1]) + (d11 < ac[2*nt+1]);
        }

    __syncthreads();
    #pragma unroll
    for (int mt = 0; mt < 4; mt++) {
        int r = warp_m * 64 + mt * 16 + frag_r;
        atomicAdd(&scnt[r], rc[2 * mt]);
        atomicAdd(&scnt[r + 8], rc[2 * mt + 1]);
    }
    if (bi != bj) {
        #pragma unroll
        for (int nt = 0; nt < 4; nt++) {
            int c = warp_n * 32 + nt * 8 + 2 * frag_k;
            atomicAdd(&scnt[128 + c], cc[2 * nt]);
            atomicAdd(&scnt[128 + c + 1], cc[2 * nt + 1]);
        }
    }
    __syncthreads();
    if (tid < 128) atomicAdd(&g_cnt[row0 + tid], scnt[tid]);
    else if (bi != bj) atomicAdd(&g_cnt[col0 + tid - 128], scnt[tid]);
}

// ---------------- kernel 5: finalize ----------------
__device__ double digamma_d(double x) {
    double r = 0.0;
    while (x < 6.0) { r -= 1.0 / x; x += 1.0; }
    double f = 1.0 / (x * x);
    double ser = f * (1.0 / 12.0 - f * (1.0 / 120.0 - f * (1.0 / 252.0
               - f * (1.0 / 240.0 - f * (1.0 / 132.0)))));
    return r + log(x) - 0.5 / x - ser;
}

__global__ void fin_part_kernel() {
    __shared__ double sd[128];
    const int tid = threadIdx.x;
    int r = blockIdx.x * 128 + tid;
    float arg = (float)(g_cnt[r] - 1) + 1e-7f;
    sd[tid] = digamma_d((double)arg);
    __syncthreads();
    for (int off = 64; off; off >>= 1) {
        if (tid < off) sd[tid] += sd[tid + off];
        __syncthreads();
    }
    if (tid == 0) g_part[blockIdx.x] = sd[0];
}

__global__ void fin2_kernel(const int* __restrict__ y, float* __restrict__ out) {
    __shared__ int hist[NCLS];
    const int tid = threadIdx.x;
    if (tid < NCLS) hist[tid] = 0;
    __syncthreads();
    for (int j = tid; j < NPTS; j += 256) atomicAdd(&hist[y[j]], 1);
    __syncthreads();
    if (tid == 0) {
        double s = 0.0;
        for (int b = 0; b < 64; b++) s += g_part[b];
        double avg_m = s / (double)NPTS;
        double avg_Nx = 0.0;
        for (int c = 0; c < NCLS; c++) {
            double nx = (double)hist[c];
            avg_Nx += (nx / (double)NPTS) * digamma_d(nx);
        }
        double mi = (digamma_d((double)NPTS) - avg_Nx
                   + digamma_d((double)KNN) - avg_m) / log(2.0);
        if (mi < 0.0) mi = 0.0;
        out[0] = (float)mi;
    }
}

// ---------------- launch ----------------
extern "C" void kernel_launch(void* const* d_in, const int* in_sizes, int n_in,
                              void* d_out, int out_size) {
    const float* X = (const float*)d_in[0];
    const int*   y = (const int*)d_in[1];
    float* out = (float*)d_out;
    (void)in_sizes; (void)n_in; (void)out_size;

    cudaFuncSetAttribute(classA_kernel, cudaFuncAttributeMaxDynamicSharedMemorySize, GSMEM);
    cudaFuncSetAttribute(gemmB_kernel,  cudaFuncAttributeMaxDynamicSharedMemorySize, GSMEM);

    prep_kernel<<<NPTS / 8, 256>>>(X);
    perm_kernel<<<1, 1024>>>(y);
    classA_kernel<<<NCLS * CTRI, 256, GSMEM>>>();
    anchor_kernel<<<NPTS / 8, 256>>>();
    gemmB_kernel<<<NTRI, 256, GSMEM>>>();
    fin_part_kernel<<<64, 128>>>();
    fin2_kernel<<<1, 256>>>(y, out);
}